// round 14
// baseline (speedup 1.0000x reference)
#include <cuda_runtime.h>
#include <cuda_fp8.h>
#include <math.h>
#include <stdint.h>

#define BATCH 1024
#define HID   4096
#define NOUT  5

#define NH_LOG2PI (-0.9189385332046727)
#define NH_LOG2PI_F (-0.91893853f)
#define PI_D 3.141592653589793238462643383279502884
#define HSCALE 64.0f

// ---------------- scratch --------------------------------------------------
__device__ __align__(16) uint8_t g_x8[BATCH * HID];    // fp8 x, [M,K]
__device__ __align__(16) uint8_t g_w1t[HID * HID];     // fp8 W1^T, [N,K]
__device__ __align__(16) uint8_t g_w2t[HID * HID];     // fp8 W2^T, [N,K]
__device__ __align__(16) uint8_t g_h1[BATCH * HID];    // fp8 h1*64, [M,K]
__device__ float g_yp[BATCH * NOUT];                    // head partial dots
__device__ double g_acc[8];

// ---------------- fp8 helpers ------------------------------------------------
__device__ __forceinline__ uint16_t f2x_fp8(float a, float b) {
    return (uint16_t)__nv_cvt_float2_to_fp8x2(make_float2(a, b), __NV_SATFINITE, __NV_E4M3);
}
__device__ __forceinline__ uint32_t f4_fp8(float a, float b, float c, float d) {
    return (uint32_t)f2x_fp8(a, b) | ((uint32_t)f2x_fp8(c, d) << 16);
}

// ---------------- small kernels ---------------------------------------------
__global__ void zero_acc_kernel() { if (threadIdx.x < 8) g_acc[threadIdx.x] = 0.0; }

__global__ void zero_yp_kernel() {
    int i = blockIdx.x * blockDim.x + threadIdx.x;
    if (i < BATCH * NOUT) g_yp[i] = 0.0f;
}

// W [K,N] fp32 -> Wt [N,K] fp8 (fused ssq when slot >= 0).
__global__ void wconv_kernel(const float* __restrict__ W, uint8_t* __restrict__ Wt,
                             int slot, int nOff) {
    __shared__ float tile[128][33];
    __shared__ float warpS[8];
    int tx = threadIdx.x, ty = threadIdx.y;
    int nb = nOff + blockIdx.x * 32, kb = blockIdx.y * 128;
    float ss = 0.0f;
    #pragma unroll
    for (int j = 0; j < 16; j++) {
        int kk = ty + 8 * j;
        float v = W[(size_t)(kb + kk) * HID + nb + tx];
        tile[kk][tx] = v;
        ss += v * v;
    }
    if (slot >= 0) {
        #pragma unroll
        for (int o = 16; o; o >>= 1) ss += __shfl_down_sync(0xffffffffu, ss, o);
        if (tx == 0) warpS[ty] = ss;
    }
    __syncthreads();
    #pragma unroll
    for (int j = 0; j < 4; j++) {
        int nn = ty + 8 * j;
        uint32_t p = f4_fp8(tile[tx * 4][nn], tile[tx * 4 + 1][nn],
                            tile[tx * 4 + 2][nn], tile[tx * 4 + 3][nn]);
        *reinterpret_cast<uint32_t*>(Wt + (size_t)(nb + nn) * HID + kb + tx * 4) = p;
    }
    if (slot >= 0 && tx == 0 && ty == 0) {
        double t = 0.0;
        #pragma unroll
        for (int w = 0; w < 8; w++) t += (double)warpS[w];
        atomicAdd(&g_acc[slot], t);
    }
}

// x fp32 -> fp8 [M,K]
__global__ void xconv_kernel(const float4* __restrict__ src, uint4* __restrict__ dst) {
    int i = blockIdx.x * blockDim.x + threadIdx.x;
    float4 a = src[4 * i], b = src[4 * i + 1], c = src[4 * i + 2], d = src[4 * i + 3];
    uint4 o;
    o.x = f4_fp8(a.x, a.y, a.z, a.w);
    o.y = f4_fp8(b.x, b.y, b.z, b.w);
    o.z = f4_fp8(c.x, c.y, c.z, c.w);
    o.w = f4_fp8(d.x, d.y, d.z, d.w);
    dst[i] = o;
}

__global__ void sumsq_kernel(const float4* __restrict__ p, int n4, int slot) {
    double local = 0.0;
    for (int i = blockIdx.x * blockDim.x + threadIdx.x; i < n4; i += gridDim.x * blockDim.x) {
        float4 v = p[i];
        local += (double)v.x * v.x + (double)v.y * v.y + (double)v.z * v.z + (double)v.w * v.w;
    }
    #pragma unroll
    for (int o = 16; o; o >>= 1) local += __shfl_down_sync(0xffffffffu, local, o);
    __shared__ double s[8];
    int lane = threadIdx.x & 31, warp = threadIdx.x >> 5;
    if (lane == 0) s[warp] = local;
    __syncthreads();
    if (threadIdx.x == 0) {
        double t = 0.0;
        int nw = blockDim.x >> 5;
        for (int w = 0; w < nw; w++) t += s[w];
        atomicAdd(&g_acc[slot], t);
    }
}

// fp32 transcendentals (MUFU), fp64 accumulation, grid-wide.
__global__ void rho_kernel(const float* __restrict__ w3_mu, const float* __restrict__ w3_rho,
                           const float* __restrict__ b3_mu, const float* __restrict__ b3_rho) {
    double lvp = 0.0, lp = 0.0;
    int gid = blockIdx.x * blockDim.x + threadIdx.x;
    int stride = gridDim.x * blockDim.x;
    for (int i = gid; i < NOUT * HID; i += stride) {
        float r = w3_rho[i];
        float sw = log1pf(__expf(r));
        lvp += (double)(NH_LOG2PI_F - __logf(sw));
        float m = w3_mu[i];
        lp += (double)(NH_LOG2PI_F - 0.5f * m * m);
    }
    if (gid < NOUT) {
        float r = b3_rho[gid];
        float sb = log1pf(__expf(r));
        lvp += (double)(NH_LOG2PI_F - __logf(sb));
        float m = b3_mu[gid];
        lp += (double)(NH_LOG2PI_F - 0.5f * m * m);
    }
    #pragma unroll
    for (int o = 16; o; o >>= 1) {
        lvp += __shfl_down_sync(0xffffffffu, lvp, o);
        lp  += __shfl_down_sync(0xffffffffu, lp, o);
    }
    __shared__ double sv[8], sp[8];
    int lane = threadIdx.x & 31, warp = threadIdx.x >> 5;
    if (lane == 0) { sv[warp] = lvp; sp[warp] = lp; }
    __syncthreads();
    if (threadIdx.x == 0) {
        double a = 0.0, b = 0.0;
        int nw = blockDim.x >> 5;
        for (int w = 0; w < nw; w++) { a += sv[w]; b += sp[w]; }
        atomicAdd(&g_acc[4], a);
        atomicAdd(&g_acc[5], b);
    }
}

__device__ __forceinline__ double log_C_vmf(double d, double kappa) {
    double s  = 0.5 * d - 1.0;
    double x  = kappa / s;
    double sq = sqrt(1.0 + x * x);
    double eta = sq + log(x) - log1p(sq);
    double logI = s * eta - 0.5 * log(2.0 * PI_D * s) - 0.5 * log(sq);
    return d * NH_LOG2PI + s * log(kappa) - logI;
}
__device__ __forceinline__ double log_surface_area(double dim) {
    double h = (dim + 1.0) * 0.5;
    float hf = (float)h;
    return log(2.0) + h * log(PI_D) - lgamma((double)hf);
}

__global__ void scalars_kernel(const float* lkw1, const float* lkb1,
                               const float* lkw2, const float* lkb2,
                               float* __restrict__ out) {
    double kw1 = exp((double)lkw1[0]) + 1e-6;
    double kb1 = exp((double)lkb1[0]) + 1e-6;
    double kw2 = exp((double)lkw2[0]) + 1e-6;
    double kb2 = exp((double)lkb2[0]) + 1e-6;
    const double dw = 4096.0 * 4096.0;
    const double db = 4096.0;
    double lvp = kw1 + log_C_vmf(dw, kw1) + kb1 + log_C_vmf(db, kb1)
               + kw2 + log_C_vmf(dw, kw2) + kb2 + log_C_vmf(db, kb2)
               + g_acc[4];
    double lp = -4.0 * log_surface_area(dw) + g_acc[5];   // source bug preserved
    out[BATCH * NOUT + 0] = (float)lvp;
    out[BATCH * NOUT + 1] = (float)lp;
}

// ---------------- fp8 pipelined mma.sync GEMM, 64x64 tiles --------------------
#define KCHUNK 128
#define NITER  (HID / KCHUNK)
#define T_ROWB 144
#define A_TILE (64 * T_ROWB)
#define B_TILE (64 * T_ROWB)
#define STAGE_BYTES (A_TILE + B_TILE)
#define GEMM_SMEM (3 * STAGE_BYTES)

__device__ __forceinline__ void cp16(uint32_t dst, const void* src) {
    asm volatile("cp.async.cg.shared.global [%0], [%1], 16;" :: "r"(dst), "l"(src) : "memory");
}
__device__ __forceinline__ void ldsm_x4(uint32_t* r, uint32_t addr) {
    asm volatile("ldmatrix.sync.aligned.m8n8.x4.shared.b16 {%0,%1,%2,%3}, [%4];"
                 : "=r"(r[0]), "=r"(r[1]), "=r"(r[2]), "=r"(r[3]) : "r"(addr));
}
__device__ __forceinline__ void mma_fp8(float* c, const uint32_t* a, const uint32_t* b) {
    asm volatile("mma.sync.aligned.m16n8k32.row.col.f32.e4m3.e4m3.f32 "
                 "{%0,%1,%2,%3},{%4,%5,%6,%7},{%8,%9},{%0,%1,%2,%3};"
                 : "+f"(c[0]), "+f"(c[1]), "+f"(c[2]), "+f"(c[3])
                 : "r"(a[0]), "r"(a[1]), "r"(a[2]), "r"(a[3]), "r"(b[0]), "r"(b[1]));
}

__device__ __forceinline__ void load_stage(uint32_t sA, uint32_t sB,
                                           const uint8_t* __restrict__ A,
                                           const uint8_t* __restrict__ Bt,
                                           int mBase, int nBase, int kt, int tid) {
    #pragma unroll
    for (int j = 0; j < 4; j++) {
        int i = tid + j * 128;
        int r = i >> 3, c = i & 7;
        cp16(sA + r * T_ROWB + c * 16, A + (size_t)(mBase + r) * HID + kt + c * 16);
    }
    #pragma unroll
    for (int j = 0; j < 4; j++) {
        int i = tid + j * 128;
        int r = i >> 3, c = i & 7;
        cp16(sB + r * T_ROWB + c * 16, Bt + (size_t)(nBase + r) * HID + kt + c * 16);
    }
    asm volatile("cp.async.commit_group;" ::: "memory");
}

// mode 0: layer1, writes fp8 h1*HSCALE.  mode 1: layer2, fused head partial dots.
__global__ void __launch_bounds__(128) gemm_fp8_kernel(
    const uint8_t* __restrict__ A, const uint8_t* __restrict__ Bt,
    const float* __restrict__ bias, const float* __restrict__ w3,
    int mode, float aScale, int slotW, int slotB, int mOff)
{
    extern __shared__ char smraw[];
    uint32_t smem = (uint32_t)__cvta_generic_to_shared(smraw);
    __shared__ float w3s[NOUT][64];

    const int tid  = threadIdx.x;
    const int lane = tid & 31, warp = tid >> 5;
    const int mBase = mOff + blockIdx.x * 64;
    const int nBase = blockIdx.y * 64;
    const int wm = (warp >> 1) * 32;
    const int wn = (warp & 1) * 32;

    if (mode == 1) {
        for (int i = tid; i < NOUT * 64; i += 128) {
            int o = i >> 6, c = i & 63;
            w3s[o][c] = w3[o * HID + nBase + c];
        }
    }

    float acc[2][4][4];
    #pragma unroll
    for (int i = 0; i < 2; i++)
        #pragma unroll
        for (int j = 0; j < 4; j++)
            #pragma unroll
            for (int k = 0; k < 4; k++) acc[i][j][k] = 0.0f;

    load_stage(smem, smem + A_TILE, A, Bt, mBase, nBase, 0, tid);
    load_stage(smem + STAGE_BYTES, smem + STAGE_BYTES + A_TILE, A, Bt, mBase, nBase, KCHUNK, tid);

    const uint32_t aLane = (uint32_t)((wm + (lane & 15)) * T_ROWB + (lane >> 4) * 16);
    const uint32_t bLane = (uint32_t)((lane & 15) * T_ROWB + (lane >> 4) * 16);

    for (int it = 0; it < NITER; ++it) {
        if (it == NITER - 1)
            asm volatile("cp.async.wait_group 0;" ::: "memory");
        else
            asm volatile("cp.async.wait_group 1;" ::: "memory");
        __syncthreads();

        if (it + 2 < NITER) {
            uint32_t s = smem + (uint32_t)((it + 2) % 3) * STAGE_BYTES;
            load_stage(s, s + A_TILE, A, Bt, mBase, nBase, (it + 2) * KCHUNK, tid);
        }

        uint32_t sA = smem + (uint32_t)(it % 3) * STAGE_BYTES;
        uint32_t sB = sA + A_TILE;

        #pragma unroll
        for (int ks = 0; ks < 4; ks++) {
            uint32_t af[2][4], bfr[4][2];
            #pragma unroll
            for (int mi = 0; mi < 2; mi++)
                ldsm_x4(af[mi], sA + aLane + (uint32_t)(mi * 16 * T_ROWB + ks * 32));
            #pragma unroll
            for (int ni = 0; ni < 2; ni++) {
                uint32_t r[4];
                ldsm_x4(r, sB + bLane + (uint32_t)((wn + ni * 16) * T_ROWB + ks * 32));
                bfr[2 * ni][0] = r[0]; bfr[2 * ni][1] = r[2];
                bfr[2 * ni + 1][0] = r[1]; bfr[2 * ni + 1][1] = r[3];
            }
            #pragma unroll
            for (int mi = 0; mi < 2; mi++)
                #pragma unroll
                for (int nf = 0; nf < 4; nf++)
                    mma_fp8(acc[mi][nf], af[mi], bfr[nf]);
        }
    }

    float invW = (float)rsqrt(g_acc[slotW]) * aScale;
    float invB = (float)rsqrt(g_acc[slotB]);
    int r0 = mBase + wm + (lane >> 2);
    int c0 = nBase + wn + (lane & 3) * 2;

    if (mode == 0) {
        #pragma unroll
        for (int mi = 0; mi < 2; mi++) {
            #pragma unroll
            for (int nf = 0; nf < 4; nf++) {
                int row = r0 + mi * 16;
                int col = c0 + nf * 8;
                float bb0 = bias[col] * invB;
                float bb1 = bias[col + 1] * invB;
                float v00 = fmaxf(acc[mi][nf][0] * invW + bb0, 0.0f);
                float v01 = fmaxf(acc[mi][nf][1] * invW + bb1, 0.0f);
                float v10 = fmaxf(acc[mi][nf][2] * invW + bb0, 0.0f);
                float v11 = fmaxf(acc[mi][nf][3] * invW + bb1, 0.0f);
                *reinterpret_cast<uint16_t*>(g_h1 + (size_t)row * HID + col) =
                    f2x_fp8(v00 * HSCALE, v01 * HSCALE);
                *reinterpret_cast<uint16_t*>(g_h1 + (size_t)(row + 8) * HID + col) =
                    f2x_fp8(v10 * HSCALE, v11 * HSCALE);
            }
        }
    } else {
        float p[4][NOUT];
        #pragma unroll
        for (int r = 0; r < 4; r++)
            #pragma unroll
            for (int o = 0; o < NOUT; o++) p[r][o] = 0.0f;
        #pragma unroll
        for (int mi = 0; mi < 2; mi++) {
            #pragma unroll
            for (int nf = 0; nf < 4; nf++) {
                int col = c0 + nf * 8;
                int cl = col - nBase;
                float bb0 = bias[col] * invB;
                float bb1 = bias[col + 1] * invB;
                float v00 = fmaxf(acc[mi][nf][0] * invW + bb0, 0.0f);
                float v01 = fmaxf(acc[mi][nf][1] * invW + bb1, 0.0f);
                float v10 = fmaxf(acc[mi][nf][2] * invW + bb0, 0.0f);
                float v11 = fmaxf(acc[mi][nf][3] * invW + bb1, 0.0f);
                #pragma unroll
                for (int o = 0; o < NOUT; o++) {
                    float w0 = w3s[o][cl], w1v = w3s[o][cl + 1];
                    p[mi * 2][o]     += v00 * w0 + v01 * w1v;
                    p[mi * 2 + 1][o] += v10 * w0 + v11 * w1v;
                }
            }
        }
        #pragma unroll
        for (int m = 1; m < 4; m <<= 1)
            #pragma unroll
            for (int r = 0; r < 4; r++)
                #pragma unroll
                for (int o = 0; o < NOUT; o++)
                    p[r][o] += __shfl_xor_sync(0xffffffffu, p[r][o], m);
        if ((lane & 3) == 0) {
            #pragma unroll
            for (int r = 0; r < 4; r++) {
                int row = r0 + (r & 1) * 8 + (r >> 1) * 16;
                #pragma unroll
                for (int o = 0; o < NOUT; o++)
                    atomicAdd(&g_yp[row * NOUT + o], p[(r >> 1) * 2 + (r & 1)][o]);
            }
        }
    }
}

// ---------------- final head: bias + log_softmax ------------------------------
__global__ void head_final_kernel(const float* __restrict__ b3, float* __restrict__ out) {
    int r = blockIdx.x * blockDim.x + threadIdx.x;
    if (r >= BATCH) return;
    float y[NOUT];
    #pragma unroll
    for (int o = 0; o < NOUT; o++) y[o] = g_yp[r * NOUT + o] + b3[o];
    float m = y[0];
    #pragma unroll
    for (int o = 1; o < NOUT; o++) m = fmaxf(m, y[o]);
    float s = 0.f;
    #pragma unroll
    for (int o = 0; o < NOUT; o++) s += expf(y[o] - m);
    float lse = m + logf(s);
    #pragma unroll
    for (int o = 0; o < NOUT; o++) out[r * NOUT + o] = y[o] - lse;
}

// ---------------- launch -----------------------------------------------------
#define NCHUNK 4

extern "C" void kernel_launch(void* const* d_in, const int* in_sizes, int n_in,
                              void* d_out, int out_size) {
    const float* x    = (const float*)d_in[0];
    const float* w1   = (const float*)d_in[1];
    const float* lk1w = (const float*)d_in[2];
    const float* b1   = (const float*)d_in[3];
    const float* lk1b = (const float*)d_in[4];
    const float* w2   = (const float*)d_in[5];
    const float* lk2w = (const float*)d_in[6];
    const float* b2   = (const float*)d_in[7];
    const float* lk2b = (const float*)d_in[8];
    const float* w3   = (const float*)d_in[9];
    const float* w3r  = (const float*)d_in[10];
    const float* b3   = (const float*)d_in[11];
    const float* b3r  = (const float*)d_in[12];
    float* out = (float*)d_out;

    // EXACTLY 3 created streams (round-12 budget; more trips the mem guard)
    static cudaStream_t s2 = nullptr, s3 = nullptr, s4 = nullptr;
    static cudaEvent_t evF = nullptr, evS3 = nullptr, evW1a = nullptr, evW1b = nullptr,
                       evPrep2 = nullptr, evScal = nullptr, evG2[NCHUNK] = {};
    static int init_done = 0;
    if (!init_done) {
        cudaFuncSetAttribute(gemm_fp8_kernel, cudaFuncAttributeMaxDynamicSharedMemorySize, GEMM_SMEM);
        cudaStreamCreateWithFlags(&s2, cudaStreamNonBlocking);
        cudaStreamCreateWithFlags(&s3, cudaStreamNonBlocking);
        cudaStreamCreateWithFlags(&s4, cudaStreamNonBlocking);
        cudaEventCreateWithFlags(&evF, cudaEventDisableTiming);
        cudaEventCreateWithFlags(&evS3, cudaEventDisableTiming);
        cudaEventCreateWithFlags(&evW1a, cudaEventDisableTiming);
        cudaEventCreateWithFlags(&evW1b, cudaEventDisableTiming);
        cudaEventCreateWithFlags(&evPrep2, cudaEventDisableTiming);
        cudaEventCreateWithFlags(&evScal, cudaEventDisableTiming);
        for (int c = 0; c < NCHUNK; c++) cudaEventCreateWithFlags(&evG2[c], cudaEventDisableTiming);
        init_done = 1;
    }

    cudaStream_t ms = cudaStreamLegacy;
    {
        cudaStreamCaptureStatus st = cudaStreamCaptureStatusNone;
        cudaStreamIsCapturing(cudaStreamLegacy, &st);
        if (st != cudaStreamCaptureStatusActive) {
            cudaStreamCaptureStatus st2 = cudaStreamCaptureStatusNone;
            cudaStreamIsCapturing(cudaStreamPerThread, &st2);
            if (st2 == cudaStreamCaptureStatusActive) ms = cudaStreamPerThread;
        }
    }

    uint8_t *x8_p, *w1t_p, *w2t_p, *h1_p;
    cudaGetSymbolAddress((void**)&x8_p, g_x8);
    cudaGetSymbolAddress((void**)&w1t_p, g_w1t);
    cudaGetSymbolAddress((void**)&w2t_p, g_w2t);
    cudaGetSymbolAddress((void**)&h1_p, g_h1);

    dim3 wblk(32, 8);
    dim3 wgridHalf(HID / 64, HID / 128);
    dim3 wgridFull(HID / 32, HID / 128);
    dim3 gridChunk(BATCH / (64 * NCHUNK), HID / 64);   // 4 x 64 = 256 CTAs per chunk

    // fork: accumulator zeroing gates the wconv atomics
    zero_acc_kernel<<<1, 32, 0, ms>>>();
    cudaEventRecord(evF, ms);
    cudaStreamWaitEvent(s2, evF, 0);
    cudaStreamWaitEvent(s3, evF, 0);

    // s3: yp zeroing (gates g2), ssq(b1), x conversion
    zero_yp_kernel<<<(BATCH * NOUT + 255) / 256, 256, 0, s3>>>();
    sumsq_kernel<<<8, 256, 0, s3>>>((const float4*)b1, HID / 4, 1);
    xconv_kernel<<<(BATCH * HID / 16) / 256, 256, 0, s3>>>((const float4*)x, (uint4*)x8_p);
    cudaEventRecord(evS3, s3);

    // ms: wconv1 half 0 (fused ssq slot 0)
    wconv_kernel<<<wgridHalf, wblk, 0, ms>>>(w1, w1t_p, 0, 0);
    cudaEventRecord(evW1a, ms);

    // s2: wconv1 half 1 (fused ssq), then gemm2 prep, then rho+scalars (off-tail)
    wconv_kernel<<<wgridHalf, wblk, 0, s2>>>(w1, w1t_p, 0, HID / 2);
    cudaEventRecord(evW1b, s2);
    wconv_kernel<<<wgridFull, wblk, 0, s2>>>(w2, w2t_p, 2, 0);
    sumsq_kernel<<<8, 256, 0, s2>>>((const float4*)b2, HID / 4, 3);
    cudaEventRecord(evPrep2, s2);
    rho_kernel<<<80, 256, 0, s2>>>(w3, w3r, b3, b3r);
    scalars_kernel<<<1, 1, 0, s2>>>(lk1w, lk1b, lk2w, lk2b, out);
    cudaEventRecord(evScal, s2);

    // 4 chunk chains mapped onto existing streams: ms, s4, s3, s2
    cudaStream_t chainStream[NCHUNK] = { ms, s4, s3, s2 };
    for (int c = 0; c < NCHUNK; c++) {
        cudaStream_t st = chainStream[c];
        if (st != ms) cudaStreamWaitEvent(st, evW1a, 0);
        if (st != s3) cudaStreamWaitEvent(st, evS3, 0);
        if (st != s2) cudaStreamWaitEvent(st, evW1b, 0);
        int mOff = c * (BATCH / NCHUNK);
        gemm_fp8_kernel<<<gridChunk, 128, GEMM_SMEM, st>>>(
            x8_p, w1t_p, b1, w3, 0, 1.0f, 0, 1, mOff);
        if (st != s2) cudaStreamWaitEvent(st, evPrep2, 0);
        gemm_fp8_kernel<<<gridChunk, 128, GEMM_SMEM, st>>>(
            h1_p, w2t_p, b2, w3, 1, 1.0f / HSCALE, 2, 3, mOff);
        if (st != ms) cudaEventRecord(evG2[c], st);
    }

    // ms: join all g2 chunks + scalars branch, then final head
    for (int c = 1; c < NCHUNK; c++) cudaStreamWaitEvent(ms, evG2[c], 0);
    head_final_kernel<<<BATCH / 128, 128, 0, ms>>>(b3, out);
    cudaStreamWaitEvent(ms, evScal, 0);
}

// round 15
// speedup vs baseline: 1.0679x; 1.0679x over previous
#include <cuda_runtime.h>
#include <cuda_fp8.h>
#include <math.h>
#include <stdint.h>

#define BATCH 1024
#define HID   4096
#define NOUT  5

#define NH_LOG2PI (-0.9189385332046727)
#define NH_LOG2PI_F (-0.91893853f)
#define PI_D 3.141592653589793238462643383279502884
#define HSCALE 64.0f

// ---------------- scratch --------------------------------------------------
__device__ __align__(16) uint8_t g_x8[BATCH * HID];    // fp8 x, [M,K]
__device__ __align__(16) uint8_t g_w1t[HID * HID];     // fp8 W1^T, [N,K]
__device__ __align__(16) uint8_t g_w2t[HID * HID];     // fp8 W2^T, [N,K]
__device__ __align__(16) uint8_t g_h1[BATCH * HID];    // fp8 h1*64, [M,K]
__device__ float g_yp[BATCH * NOUT];                    // head partial dots
__device__ double g_acc[8];

// ---------------- fp8 helpers ------------------------------------------------
__device__ __forceinline__ uint16_t f2x_fp8(float a, float b) {
    return (uint16_t)__nv_cvt_float2_to_fp8x2(make_float2(a, b), __NV_SATFINITE, __NV_E4M3);
}
__device__ __forceinline__ uint32_t f4_fp8(float a, float b, float c, float d) {
    return (uint32_t)f2x_fp8(a, b) | ((uint32_t)f2x_fp8(c, d) << 16);
}

// ---------------- small kernels ---------------------------------------------
__global__ void zero_acc_kernel() { if (threadIdx.x < 8) g_acc[threadIdx.x] = 0.0; }

__global__ void zero_yp_kernel() {
    int i = blockIdx.x * blockDim.x + threadIdx.x;
    if (i < BATCH * NOUT) g_yp[i] = 0.0f;
}

// W [K,N] fp32 -> Wt [N,K] fp8 (fused ssq when slot >= 0).
__global__ void wconv_kernel(const float* __restrict__ W, uint8_t* __restrict__ Wt,
                             int slot, int nOff) {
    __shared__ float tile[128][33];
    __shared__ float warpS[8];
    int tx = threadIdx.x, ty = threadIdx.y;
    int nb = nOff + blockIdx.x * 32, kb = blockIdx.y * 128;
    float ss = 0.0f;
    #pragma unroll
    for (int j = 0; j < 16; j++) {
        int kk = ty + 8 * j;
        float v = W[(size_t)(kb + kk) * HID + nb + tx];
        tile[kk][tx] = v;
        ss += v * v;
    }
    if (slot >= 0) {
        #pragma unroll
        for (int o = 16; o; o >>= 1) ss += __shfl_down_sync(0xffffffffu, ss, o);
        if (tx == 0) warpS[ty] = ss;
    }
    __syncthreads();
    #pragma unroll
    for (int j = 0; j < 4; j++) {
        int nn = ty + 8 * j;
        uint32_t p = f4_fp8(tile[tx * 4][nn], tile[tx * 4 + 1][nn],
                            tile[tx * 4 + 2][nn], tile[tx * 4 + 3][nn]);
        *reinterpret_cast<uint32_t*>(Wt + (size_t)(nb + nn) * HID + kb + tx * 4) = p;
    }
    if (slot >= 0 && tx == 0 && ty == 0) {
        double t = 0.0;
        #pragma unroll
        for (int w = 0; w < 8; w++) t += (double)warpS[w];
        atomicAdd(&g_acc[slot], t);
    }
}

// x fp32 -> fp8 [M,K]
__global__ void xconv_kernel(const float4* __restrict__ src, uint4* __restrict__ dst) {
    int i = blockIdx.x * blockDim.x + threadIdx.x;
    float4 a = src[4 * i], b = src[4 * i + 1], c = src[4 * i + 2], d = src[4 * i + 3];
    uint4 o;
    o.x = f4_fp8(a.x, a.y, a.z, a.w);
    o.y = f4_fp8(b.x, b.y, b.z, b.w);
    o.z = f4_fp8(c.x, c.y, c.z, c.w);
    o.w = f4_fp8(d.x, d.y, d.z, d.w);
    dst[i] = o;
}

__global__ void sumsq_kernel(const float4* __restrict__ p, int n4, int slot) {
    double local = 0.0;
    for (int i = blockIdx.x * blockDim.x + threadIdx.x; i < n4; i += gridDim.x * blockDim.x) {
        float4 v = p[i];
        local += (double)v.x * v.x + (double)v.y * v.y + (double)v.z * v.z + (double)v.w * v.w;
    }
    #pragma unroll
    for (int o = 16; o; o >>= 1) local += __shfl_down_sync(0xffffffffu, local, o);
    __shared__ double s[8];
    int lane = threadIdx.x & 31, warp = threadIdx.x >> 5;
    if (lane == 0) s[warp] = local;
    __syncthreads();
    if (threadIdx.x == 0) {
        double t = 0.0;
        int nw = blockDim.x >> 5;
        for (int w = 0; w < nw; w++) t += s[w];
        atomicAdd(&g_acc[slot], t);
    }
}

// fp32 transcendentals (MUFU), fp64 accumulation, grid-wide.
__global__ void rho_kernel(const float* __restrict__ w3_mu, const float* __restrict__ w3_rho,
                           const float* __restrict__ b3_mu, const float* __restrict__ b3_rho) {
    double lvp = 0.0, lp = 0.0;
    int gid = blockIdx.x * blockDim.x + threadIdx.x;
    int stride = gridDim.x * blockDim.x;
    for (int i = gid; i < NOUT * HID; i += stride) {
        float r = w3_rho[i];
        float sw = log1pf(__expf(r));
        lvp += (double)(NH_LOG2PI_F - __logf(sw));
        float m = w3_mu[i];
        lp += (double)(NH_LOG2PI_F - 0.5f * m * m);
    }
    if (gid < NOUT) {
        float r = b3_rho[gid];
        float sb = log1pf(__expf(r));
        lvp += (double)(NH_LOG2PI_F - __logf(sb));
        float m = b3_mu[gid];
        lp += (double)(NH_LOG2PI_F - 0.5f * m * m);
    }
    #pragma unroll
    for (int o = 16; o; o >>= 1) {
        lvp += __shfl_down_sync(0xffffffffu, lvp, o);
        lp  += __shfl_down_sync(0xffffffffu, lp, o);
    }
    __shared__ double sv[8], sp[8];
    int lane = threadIdx.x & 31, warp = threadIdx.x >> 5;
    if (lane == 0) { sv[warp] = lvp; sp[warp] = lp; }
    __syncthreads();
    if (threadIdx.x == 0) {
        double a = 0.0, b = 0.0;
        int nw = blockDim.x >> 5;
        for (int w = 0; w < nw; w++) { a += sv[w]; b += sp[w]; }
        atomicAdd(&g_acc[4], a);
        atomicAdd(&g_acc[5], b);
    }
}

__device__ __forceinline__ double log_C_vmf(double d, double kappa) {
    double s  = 0.5 * d - 1.0;
    double x  = kappa / s;
    double sq = sqrt(1.0 + x * x);
    double eta = sq + log(x) - log1p(sq);
    double logI = s * eta - 0.5 * log(2.0 * PI_D * s) - 0.5 * log(sq);
    return d * NH_LOG2PI + s * log(kappa) - logI;
}
__device__ __forceinline__ double log_surface_area(double dim) {
    double h = (dim + 1.0) * 0.5;
    float hf = (float)h;
    return log(2.0) + h * log(PI_D) - lgamma((double)hf);
}

__global__ void scalars_kernel(const float* lkw1, const float* lkb1,
                               const float* lkw2, const float* lkb2,
                               float* __restrict__ out) {
    double kw1 = exp((double)lkw1[0]) + 1e-6;
    double kb1 = exp((double)lkb1[0]) + 1e-6;
    double kw2 = exp((double)lkw2[0]) + 1e-6;
    double kb2 = exp((double)lkb2[0]) + 1e-6;
    const double dw = 4096.0 * 4096.0;
    const double db = 4096.0;
    double lvp = kw1 + log_C_vmf(dw, kw1) + kb1 + log_C_vmf(db, kb1)
               + kw2 + log_C_vmf(dw, kw2) + kb2 + log_C_vmf(db, kb2)
               + g_acc[4];
    double lp = -4.0 * log_surface_area(dw) + g_acc[5];   // source bug preserved
    out[BATCH * NOUT + 0] = (float)lvp;
    out[BATCH * NOUT + 1] = (float)lp;
}

// ---------------- fp8 pipelined mma.sync GEMM, 64x64 tiles --------------------
#define KCHUNK 128
#define NITER  (HID / KCHUNK)
#define T_ROWB 144
#define A_TILE (64 * T_ROWB)
#define B_TILE (64 * T_ROWB)
#define STAGE_BYTES (A_TILE + B_TILE)
#define GEMM_SMEM (3 * STAGE_BYTES)

__device__ __forceinline__ void cp16(uint32_t dst, const void* src) {
    asm volatile("cp.async.cg.shared.global [%0], [%1], 16;" :: "r"(dst), "l"(src) : "memory");
}
__device__ __forceinline__ void ldsm_x4(uint32_t* r, uint32_t addr) {
    asm volatile("ldmatrix.sync.aligned.m8n8.x4.shared.b16 {%0,%1,%2,%3}, [%4];"
                 : "=r"(r[0]), "=r"(r[1]), "=r"(r[2]), "=r"(r[3]) : "r"(addr));
}
__device__ __forceinline__ void mma_fp8(float* c, const uint32_t* a, const uint32_t* b) {
    asm volatile("mma.sync.aligned.m16n8k32.row.col.f32.e4m3.e4m3.f32 "
                 "{%0,%1,%2,%3},{%4,%5,%6,%7},{%8,%9},{%0,%1,%2,%3};"
                 : "+f"(c[0]), "+f"(c[1]), "+f"(c[2]), "+f"(c[3])
                 : "r"(a[0]), "r"(a[1]), "r"(a[2]), "r"(a[3]), "r"(b[0]), "r"(b[1]));
}

__device__ __forceinline__ void load_stage(uint32_t sA, uint32_t sB,
                                           const uint8_t* __restrict__ A,
                                           const uint8_t* __restrict__ Bt,
                                           int mBase, int nBase, int kt, int tid) {
    #pragma unroll
    for (int j = 0; j < 4; j++) {
        int i = tid + j * 128;
        int r = i >> 3, c = i & 7;
        cp16(sA + r * T_ROWB + c * 16, A + (size_t)(mBase + r) * HID + kt + c * 16);
    }
    #pragma unroll
    for (int j = 0; j < 4; j++) {
        int i = tid + j * 128;
        int r = i >> 3, c = i & 7;
        cp16(sB + r * T_ROWB + c * 16, Bt + (size_t)(nBase + r) * HID + kt + c * 16);
    }
    asm volatile("cp.async.commit_group;" ::: "memory");
}

// mode 0: layer1, writes fp8 h1*HSCALE.  mode 1: layer2, fused head partial dots.
__global__ void __launch_bounds__(128) gemm_fp8_kernel(
    const uint8_t* __restrict__ A, const uint8_t* __restrict__ Bt,
    const float* __restrict__ bias, const float* __restrict__ w3,
    int mode, float aScale, int slotW, int slotB, int mOff)
{
    extern __shared__ char smraw[];
    uint32_t smem = (uint32_t)__cvta_generic_to_shared(smraw);
    __shared__ float w3s[NOUT][64];

    const int tid  = threadIdx.x;
    const int lane = tid & 31, warp = tid >> 5;
    const int mBase = mOff + blockIdx.x * 64;
    const int nBase = blockIdx.y * 64;
    const int wm = (warp >> 1) * 32;
    const int wn = (warp & 1) * 32;

    if (mode == 1) {
        for (int i = tid; i < NOUT * 64; i += 128) {
            int o = i >> 6, c = i & 63;
            w3s[o][c] = w3[o * HID + nBase + c];
        }
    }

    float acc[2][4][4];
    #pragma unroll
    for (int i = 0; i < 2; i++)
        #pragma unroll
        for (int j = 0; j < 4; j++)
            #pragma unroll
            for (int k = 0; k < 4; k++) acc[i][j][k] = 0.0f;

    load_stage(smem, smem + A_TILE, A, Bt, mBase, nBase, 0, tid);
    load_stage(smem + STAGE_BYTES, smem + STAGE_BYTES + A_TILE, A, Bt, mBase, nBase, KCHUNK, tid);

    const uint32_t aLane = (uint32_t)((wm + (lane & 15)) * T_ROWB + (lane >> 4) * 16);
    const uint32_t bLane = (uint32_t)((lane & 15) * T_ROWB + (lane >> 4) * 16);

    for (int it = 0; it < NITER; ++it) {
        if (it == NITER - 1)
            asm volatile("cp.async.wait_group 0;" ::: "memory");
        else
            asm volatile("cp.async.wait_group 1;" ::: "memory");
        __syncthreads();

        if (it + 2 < NITER) {
            uint32_t s = smem + (uint32_t)((it + 2) % 3) * STAGE_BYTES;
            load_stage(s, s + A_TILE, A, Bt, mBase, nBase, (it + 2) * KCHUNK, tid);
        }

        uint32_t sA = smem + (uint32_t)(it % 3) * STAGE_BYTES;
        uint32_t sB = sA + A_TILE;

        #pragma unroll
        for (int ks = 0; ks < 4; ks++) {
            uint32_t af[2][4], bfr[4][2];
            #pragma unroll
            for (int mi = 0; mi < 2; mi++)
                ldsm_x4(af[mi], sA + aLane + (uint32_t)(mi * 16 * T_ROWB + ks * 32));
            #pragma unroll
            for (int ni = 0; ni < 2; ni++) {
                uint32_t r[4];
                ldsm_x4(r, sB + bLane + (uint32_t)((wn + ni * 16) * T_ROWB + ks * 32));
                bfr[2 * ni][0] = r[0]; bfr[2 * ni][1] = r[2];
                bfr[2 * ni + 1][0] = r[1]; bfr[2 * ni + 1][1] = r[3];
            }
            #pragma unroll
            for (int mi = 0; mi < 2; mi++)
                #pragma unroll
                for (int nf = 0; nf < 4; nf++)
                    mma_fp8(acc[mi][nf], af[mi], bfr[nf]);
        }
    }

    float invW = (float)rsqrt(g_acc[slotW]) * aScale;
    float invB = (float)rsqrt(g_acc[slotB]);
    int r0 = mBase + wm + (lane >> 2);
    int c0 = nBase + wn + (lane & 3) * 2;

    if (mode == 0) {
        #pragma unroll
        for (int mi = 0; mi < 2; mi++) {
            #pragma unroll
            for (int nf = 0; nf < 4; nf++) {
                int row = r0 + mi * 16;
                int col = c0 + nf * 8;
                float bb0 = bias[col] * invB;
                float bb1 = bias[col + 1] * invB;
                float v00 = fmaxf(acc[mi][nf][0] * invW + bb0, 0.0f);
                float v01 = fmaxf(acc[mi][nf][1] * invW + bb1, 0.0f);
                float v10 = fmaxf(acc[mi][nf][2] * invW + bb0, 0.0f);
                float v11 = fmaxf(acc[mi][nf][3] * invW + bb1, 0.0f);
                *reinterpret_cast<uint16_t*>(g_h1 + (size_t)row * HID + col) =
                    f2x_fp8(v00 * HSCALE, v01 * HSCALE);
                *reinterpret_cast<uint16_t*>(g_h1 + (size_t)(row + 8) * HID + col) =
                    f2x_fp8(v10 * HSCALE, v11 * HSCALE);
            }
        }
    } else {
        float p[4][NOUT];
        #pragma unroll
        for (int r = 0; r < 4; r++)
            #pragma unroll
            for (int o = 0; o < NOUT; o++) p[r][o] = 0.0f;
        #pragma unroll
        for (int mi = 0; mi < 2; mi++) {
            #pragma unroll
            for (int nf = 0; nf < 4; nf++) {
                int col = c0 + nf * 8;
                int cl = col - nBase;
                float bb0 = bias[col] * invB;
                float bb1 = bias[col + 1] * invB;
                float v00 = fmaxf(acc[mi][nf][0] * invW + bb0, 0.0f);
                float v01 = fmaxf(acc[mi][nf][1] * invW + bb1, 0.0f);
                float v10 = fmaxf(acc[mi][nf][2] * invW + bb0, 0.0f);
                float v11 = fmaxf(acc[mi][nf][3] * invW + bb1, 0.0f);
                #pragma unroll
                for (int o = 0; o < NOUT; o++) {
                    float w0 = w3s[o][cl], w1v = w3s[o][cl + 1];
                    p[mi * 2][o]     += v00 * w0 + v01 * w1v;
                    p[mi * 2 + 1][o] += v10 * w0 + v11 * w1v;
                }
            }
        }
        #pragma unroll
        for (int m = 1; m < 4; m <<= 1)
            #pragma unroll
            for (int r = 0; r < 4; r++)
                #pragma unroll
                for (int o = 0; o < NOUT; o++)
                    p[r][o] += __shfl_xor_sync(0xffffffffu, p[r][o], m);
        if ((lane & 3) == 0) {
            #pragma unroll
            for (int r = 0; r < 4; r++) {
                int row = r0 + (r & 1) * 8 + (r >> 1) * 16;
                #pragma unroll
                for (int o = 0; o < NOUT; o++)
                    atomicAdd(&g_yp[row * NOUT + o], p[(r >> 1) * 2 + (r & 1)][o]);
            }
        }
    }
}

// ---------------- final head: bias + log_softmax ------------------------------
__global__ void head_final_kernel(const float* __restrict__ b3, float* __restrict__ out) {
    int r = blockIdx.x * blockDim.x + threadIdx.x;
    if (r >= BATCH) return;
    float y[NOUT];
    #pragma unroll
    for (int o = 0; o < NOUT; o++) y[o] = g_yp[r * NOUT + o] + b3[o];
    float m = y[0];
    #pragma unroll
    for (int o = 1; o < NOUT; o++) m = fmaxf(m, y[o]);
    float s = 0.f;
    #pragma unroll
    for (int o = 0; o < NOUT; o++) s += expf(y[o] - m);
    float lse = m + logf(s);
    #pragma unroll
    for (int o = 0; o < NOUT; o++) out[r * NOUT + o] = y[o] - lse;
}

// ---------------- launch -----------------------------------------------------
extern "C" void kernel_launch(void* const* d_in, const int* in_sizes, int n_in,
                              void* d_out, int out_size) {
    const float* x    = (const float*)d_in[0];
    const float* w1   = (const float*)d_in[1];
    const float* lk1w = (const float*)d_in[2];
    const float* b1   = (const float*)d_in[3];
    const float* lk1b = (const float*)d_in[4];
    const float* w2   = (const float*)d_in[5];
    const float* lk2w = (const float*)d_in[6];
    const float* b2   = (const float*)d_in[7];
    const float* lk2b = (const float*)d_in[8];
    const float* w3   = (const float*)d_in[9];
    const float* w3r  = (const float*)d_in[10];
    const float* b3   = (const float*)d_in[11];
    const float* b3r  = (const float*)d_in[12];
    float* out = (float*)d_out;

    // 3 created streams (round-12 budget; more trips the mem guard)
    static cudaStream_t s2 = nullptr, s3 = nullptr, s4 = nullptr;
    static cudaEvent_t evF = nullptr, evS3 = nullptr, evW1a = nullptr, evW1b = nullptr,
                       evPrep2 = nullptr, evScal = nullptr, evG2h1 = nullptr;
    static int init_done = 0;
    if (!init_done) {
        cudaFuncSetAttribute(gemm_fp8_kernel, cudaFuncAttributeMaxDynamicSharedMemorySize, GEMM_SMEM);
        cudaStreamCreateWithFlags(&s2, cudaStreamNonBlocking);
        cudaStreamCreateWithFlags(&s3, cudaStreamNonBlocking);
        cudaStreamCreateWithFlags(&s4, cudaStreamNonBlocking);
        cudaEventCreateWithFlags(&evF, cudaEventDisableTiming);
        cudaEventCreateWithFlags(&evS3, cudaEventDisableTiming);
        cudaEventCreateWithFlags(&evW1a, cudaEventDisableTiming);
        cudaEventCreateWithFlags(&evW1b, cudaEventDisableTiming);
        cudaEventCreateWithFlags(&evPrep2, cudaEventDisableTiming);
        cudaEventCreateWithFlags(&evScal, cudaEventDisableTiming);
        cudaEventCreateWithFlags(&evG2h1, cudaEventDisableTiming);
        init_done = 1;
    }

    cudaStream_t ms = cudaStreamLegacy;
    {
        cudaStreamCaptureStatus st = cudaStreamCaptureStatusNone;
        cudaStreamIsCapturing(cudaStreamLegacy, &st);
        if (st != cudaStreamCaptureStatusActive) {
            cudaStreamCaptureStatus st2 = cudaStreamCaptureStatusNone;
            cudaStreamIsCapturing(cudaStreamPerThread, &st2);
            if (st2 == cudaStreamCaptureStatusActive) ms = cudaStreamPerThread;
        }
    }

    uint8_t *x8_p, *w1t_p, *w2t_p, *h1_p;
    cudaGetSymbolAddress((void**)&x8_p, g_x8);
    cudaGetSymbolAddress((void**)&w1t_p, g_w1t);
    cudaGetSymbolAddress((void**)&w2t_p, g_w2t);
    cudaGetSymbolAddress((void**)&h1_p, g_h1);

    dim3 wblk(32, 8);
    dim3 wgridHalf(HID / 64, HID / 128);
    dim3 wgridFull(HID / 32, HID / 128);
    dim3 gridHalf(BATCH / 128, HID / 64);    // 8 x 64 = 512 CTAs (512 rows)

    // fork: only the 8-double accumulator zeroing gates the wconv atomics
    zero_acc_kernel<<<1, 32, 0, ms>>>();
    cudaEventRecord(evF, ms);
    cudaStreamWaitEvent(s2, evF, 0);
    cudaStreamWaitEvent(s3, evF, 0);

    // s3: yp zeroing, ssq(b1), x conversion, then rho+scalars (all short, off-path)
    zero_yp_kernel<<<(BATCH * NOUT + 255) / 256, 256, 0, s3>>>();
    sumsq_kernel<<<8, 256, 0, s3>>>((const float4*)b1, HID / 4, 1);
    xconv_kernel<<<(BATCH * HID / 16) / 256, 256, 0, s3>>>((const float4*)x, (uint4*)x8_p);
    cudaEventRecord(evS3, s3);
    rho_kernel<<<80, 256, 0, s3>>>(w3, w3r, b3, b3r);
    scalars_kernel<<<1, 1, 0, s3>>>(lk1w, lk1b, lk2w, lk2b, out);
    cudaEventRecord(evScal, s3);

    // ms: wconv1 half 0 (fused ssq slot 0)
    wconv_kernel<<<wgridHalf, wblk, 0, ms>>>(w1, w1t_p, 0, 0);
    cudaEventRecord(evW1a, ms);

    // s2: wconv1 half 1 (fused ssq), then gemm2-side prep
    wconv_kernel<<<wgridHalf, wblk, 0, s2>>>(w1, w1t_p, 0, HID / 2);
    cudaEventRecord(evW1b, s2);
    wconv_kernel<<<wgridFull, wblk, 0, s2>>>(w2, w2t_p, 2, 0);
    sumsq_kernel<<<8, 256, 0, s2>>>((const float4*)b2, HID / 4, 3);
    cudaEventRecord(evPrep2, s2);

    // ms: g1 half 0 (rows 0-511) -> g2 half 0 (chained; overlaps g1 half 1)
    cudaStreamWaitEvent(ms, evS3, 0);
    cudaStreamWaitEvent(ms, evW1b, 0);
    gemm_fp8_kernel<<<gridHalf, 128, GEMM_SMEM, ms>>>(x8_p, w1t_p, b1, w3, 0, 1.0f, 0, 1, 0);
    cudaStreamWaitEvent(ms, evPrep2, 0);
    gemm_fp8_kernel<<<gridHalf, 128, GEMM_SMEM, ms>>>(h1_p, w2t_p, b2, w3, 1, 1.0f / HSCALE, 2, 3, 0);

    // s4: g1 half 1 (rows 512-1023) -> g2 half 1
    cudaStreamWaitEvent(s4, evF, 0);
    cudaStreamWaitEvent(s4, evS3, 0);
    cudaStreamWaitEvent(s4, evW1a, 0);
    cudaStreamWaitEvent(s4, evW1b, 0);
    gemm_fp8_kernel<<<gridHalf, 128, GEMM_SMEM, s4>>>(x8_p, w1t_p, b1, w3, 0, 1.0f, 0, 1, BATCH / 2);
    cudaStreamWaitEvent(s4, evPrep2, 0);
    gemm_fp8_kernel<<<gridHalf, 128, GEMM_SMEM, s4>>>(h1_p, w2t_p, b2, w3, 1, 1.0f / HSCALE, 2, 3, BATCH / 2);
    cudaEventRecord(evG2h1, s4);

    // ms: join both g2 halves + scalars branch, then final head
    cudaStreamWaitEvent(ms, evG2h1, 0);
    head_final_kernel<<<BATCH / 128, 128, 0, ms>>>(b3, out);
    cudaStreamWaitEvent(ms, evScal, 0);
}

// round 16
// speedup vs baseline: 1.0825x; 1.0136x over previous
#include <cuda_runtime.h>
#include <cuda_fp8.h>
#include <cuda_fp16.h>
#include <math.h>
#include <stdint.h>

#define BATCH 1024
#define HID   4096
#define NOUT  5

#define NH_LOG2PI (-0.9189385332046727)
#define NH_LOG2PI_F (-0.91893853f)
#define PI_D 3.141592653589793238462643383279502884
#define HSCALE 64.0f

// ---------------- scratch --------------------------------------------------
__device__ __align__(16) uint8_t g_x8[BATCH * HID];    // fp8 x, [M,K]
__device__ __align__(16) uint8_t g_w1t[HID * HID];     // fp8 W1^T, [N,K]
__device__ __align__(16) uint8_t g_w2t[HID * HID];     // fp8 W2^T, [N,K]
__device__ __align__(16) uint8_t g_h1[BATCH * HID];    // fp8 h1*64, [M,K]
__device__ float g_yp[BATCH * NOUT];                    // head partial dots
__device__ double g_acc[8];

// ---------------- fp8 helpers ------------------------------------------------
__device__ __forceinline__ uint16_t f2x_fp8(float a, float b) {
    return (uint16_t)__nv_cvt_float2_to_fp8x2(make_float2(a, b), __NV_SATFINITE, __NV_E4M3);
}
__device__ __forceinline__ uint32_t f4_fp8(float a, float b, float c, float d) {
    return (uint32_t)f2x_fp8(a, b) | ((uint32_t)f2x_fp8(c, d) << 16);
}

// ---------------- small kernels ---------------------------------------------
__global__ void zero_acc_kernel() { if (threadIdx.x < 8) g_acc[threadIdx.x] = 0.0; }

__global__ void zero_yp_kernel() {
    int i = blockIdx.x * blockDim.x + threadIdx.x;
    if (i < BATCH * NOUT) g_yp[i] = 0.0f;
}

// W [K,N] fp32 -> Wt [N,K] fp8 (fused ssq when slot >= 0).
__global__ void wconv_kernel(const float* __restrict__ W, uint8_t* __restrict__ Wt,
                             int slot, int nOff) {
    __shared__ float tile[128][33];
    __shared__ float warpS[8];
    int tx = threadIdx.x, ty = threadIdx.y;
    int nb = nOff + blockIdx.x * 32, kb = blockIdx.y * 128;
    float ss = 0.0f;
    #pragma unroll
    for (int j = 0; j < 16; j++) {
        int kk = ty + 8 * j;
        float v = W[(size_t)(kb + kk) * HID + nb + tx];
        tile[kk][tx] = v;
        ss += v * v;
    }
    if (slot >= 0) {
        #pragma unroll
        for (int o = 16; o; o >>= 1) ss += __shfl_down_sync(0xffffffffu, ss, o);
        if (tx == 0) warpS[ty] = ss;
    }
    __syncthreads();
    #pragma unroll
    for (int j = 0; j < 4; j++) {
        int nn = ty + 8 * j;
        uint32_t p = f4_fp8(tile[tx * 4][nn], tile[tx * 4 + 1][nn],
                            tile[tx * 4 + 2][nn], tile[tx * 4 + 3][nn]);
        *reinterpret_cast<uint32_t*>(Wt + (size_t)(nb + nn) * HID + kb + tx * 4) = p;
    }
    if (slot >= 0 && tx == 0 && ty == 0) {
        double t = 0.0;
        #pragma unroll
        for (int w = 0; w < 8; w++) t += (double)warpS[w];
        atomicAdd(&g_acc[slot], t);
    }
}

// x fp32 -> fp8 [M,K]
__global__ void xconv_kernel(const float4* __restrict__ src, uint4* __restrict__ dst) {
    int i = blockIdx.x * blockDim.x + threadIdx.x;
    float4 a = src[4 * i], b = src[4 * i + 1], c = src[4 * i + 2], d = src[4 * i + 3];
    uint4 o;
    o.x = f4_fp8(a.x, a.y, a.z, a.w);
    o.y = f4_fp8(b.x, b.y, b.z, b.w);
    o.z = f4_fp8(c.x, c.y, c.z, c.w);
    o.w = f4_fp8(d.x, d.y, d.z, d.w);
    dst[i] = o;
}

__global__ void sumsq_kernel(const float4* __restrict__ p, int n4, int slot) {
    double local = 0.0;
    for (int i = blockIdx.x * blockDim.x + threadIdx.x; i < n4; i += gridDim.x * blockDim.x) {
        float4 v = p[i];
        local += (double)v.x * v.x + (double)v.y * v.y + (double)v.z * v.z + (double)v.w * v.w;
    }
    #pragma unroll
    for (int o = 16; o; o >>= 1) local += __shfl_down_sync(0xffffffffu, local, o);
    __shared__ double s[8];
    int lane = threadIdx.x & 31, warp = threadIdx.x >> 5;
    if (lane == 0) s[warp] = local;
    __syncthreads();
    if (threadIdx.x == 0) {
        double t = 0.0;
        int nw = blockDim.x >> 5;
        for (int w = 0; w < nw; w++) t += s[w];
        atomicAdd(&g_acc[slot], t);
    }
}

// fp32 transcendentals (MUFU), fp64 accumulation, grid-wide.
__global__ void rho_kernel(const float* __restrict__ w3_mu, const float* __restrict__ w3_rho,
                           const float* __restrict__ b3_mu, const float* __restrict__ b3_rho) {
    double lvp = 0.0, lp = 0.0;
    int gid = blockIdx.x * blockDim.x + threadIdx.x;
    int stride = gridDim.x * blockDim.x;
    for (int i = gid; i < NOUT * HID; i += stride) {
        float r = w3_rho[i];
        float sw = log1pf(__expf(r));
        lvp += (double)(NH_LOG2PI_F - __logf(sw));
        float m = w3_mu[i];
        lp += (double)(NH_LOG2PI_F - 0.5f * m * m);
    }
    if (gid < NOUT) {
        float r = b3_rho[gid];
        float sb = log1pf(__expf(r));
        lvp += (double)(NH_LOG2PI_F - __logf(sb));
        float m = b3_mu[gid];
        lp += (double)(NH_LOG2PI_F - 0.5f * m * m);
    }
    #pragma unroll
    for (int o = 16; o; o >>= 1) {
        lvp += __shfl_down_sync(0xffffffffu, lvp, o);
        lp  += __shfl_down_sync(0xffffffffu, lp, o);
    }
    __shared__ double sv[8], sp[8];
    int lane = threadIdx.x & 31, warp = threadIdx.x >> 5;
    if (lane == 0) { sv[warp] = lvp; sp[warp] = lp; }
    __syncthreads();
    if (threadIdx.x == 0) {
        double a = 0.0, b = 0.0;
        int nw = blockDim.x >> 5;
        for (int w = 0; w < nw; w++) { a += sv[w]; b += sp[w]; }
        atomicAdd(&g_acc[4], a);
        atomicAdd(&g_acc[5], b);
    }
}

__device__ __forceinline__ double log_C_vmf(double d, double kappa) {
    double s  = 0.5 * d - 1.0;
    double x  = kappa / s;
    double sq = sqrt(1.0 + x * x);
    double eta = sq + log(x) - log1p(sq);
    double logI = s * eta - 0.5 * log(2.0 * PI_D * s) - 0.5 * log(sq);
    return d * NH_LOG2PI + s * log(kappa) - logI;
}
__device__ __forceinline__ double log_surface_area(double dim) {
    double h = (dim + 1.0) * 0.5;
    float hf = (float)h;
    return log(2.0) + h * log(PI_D) - lgamma((double)hf);
}

__global__ void scalars_kernel(const float* lkw1, const float* lkb1,
                               const float* lkw2, const float* lkb2,
                               float* __restrict__ out) {
    double kw1 = exp((double)lkw1[0]) + 1e-6;
    double kb1 = exp((double)lkb1[0]) + 1e-6;
    double kw2 = exp((double)lkw2[0]) + 1e-6;
    double kb2 = exp((double)lkb2[0]) + 1e-6;
    const double dw = 4096.0 * 4096.0;
    const double db = 4096.0;
    double lvp = kw1 + log_C_vmf(dw, kw1) + kb1 + log_C_vmf(db, kb1)
               + kw2 + log_C_vmf(dw, kw2) + kb2 + log_C_vmf(db, kb2)
               + g_acc[4];
    double lp = -4.0 * log_surface_area(dw) + g_acc[5];   // source bug preserved
    out[BATCH * NOUT + 0] = (float)lvp;
    out[BATCH * NOUT + 1] = (float)lp;
}

// ---------------- fp8 pipelined mma.sync GEMM, 64x64 tiles, f16 accum ---------
#define KCHUNK 128
#define NITER  (HID / KCHUNK)
#define T_ROWB 144
#define A_TILE (64 * T_ROWB)
#define B_TILE (64 * T_ROWB)
#define STAGE_BYTES (A_TILE + B_TILE)
#define GEMM_SMEM (3 * STAGE_BYTES)

__device__ __forceinline__ void cp16(uint32_t dst, const void* src) {
    asm volatile("cp.async.cg.shared.global [%0], [%1], 16;" :: "r"(dst), "l"(src) : "memory");
}
__device__ __forceinline__ void ldsm_x4(uint32_t* r, uint32_t addr) {
    asm volatile("ldmatrix.sync.aligned.m8n8.x4.shared.b16 {%0,%1,%2,%3}, [%4];"
                 : "=r"(r[0]), "=r"(r[1]), "=r"(r[2]), "=r"(r[3]) : "r"(addr));
}
// fp8 inputs, f16 accumulator: C fragment = 2 b32 regs (4 halves)
__device__ __forceinline__ void mma_fp8_f16(uint32_t* c, const uint32_t* a, const uint32_t* b) {
    asm volatile("mma.sync.aligned.m16n8k32.row.col.f16.e4m3.e4m3.f16 "
                 "{%0,%1},{%2,%3,%4,%5},{%6,%7},{%0,%1};"
                 : "+r"(c[0]), "+r"(c[1])
                 : "r"(a[0]), "r"(a[1]), "r"(a[2]), "r"(a[3]), "r"(b[0]), "r"(b[1]));
}

__device__ __forceinline__ void load_stage(uint32_t sA, uint32_t sB,
                                           const uint8_t* __restrict__ A,
                                           const uint8_t* __restrict__ Bt,
                                           int mBase, int nBase, int kt, int tid) {
    #pragma unroll
    for (int j = 0; j < 4; j++) {
        int i = tid + j * 128;
        int r = i >> 3, c = i & 7;
        cp16(sA + r * T_ROWB + c * 16, A + (size_t)(mBase + r) * HID + kt + c * 16);
    }
    #pragma unroll
    for (int j = 0; j < 4; j++) {
        int i = tid + j * 128;
        int r = i >> 3, c = i & 7;
        cp16(sB + r * T_ROWB + c * 16, Bt + (size_t)(nBase + r) * HID + kt + c * 16);
    }
    asm volatile("cp.async.commit_group;" ::: "memory");
}

// mode 0: layer1, writes fp8 h1*HSCALE.  mode 1: layer2, fused head partial dots.
__global__ void __launch_bounds__(128) gemm_fp8_kernel(
    const uint8_t* __restrict__ A, const uint8_t* __restrict__ Bt,
    const float* __restrict__ bias, const float* __restrict__ w3,
    int mode, float aScale, int slotW, int slotB, int mOff)
{
    extern __shared__ char smraw[];
    uint32_t smem = (uint32_t)__cvta_generic_to_shared(smraw);
    __shared__ float w3s[NOUT][64];

    const int tid  = threadIdx.x;
    const int lane = tid & 31, warp = tid >> 5;
    const int mBase = mOff + blockIdx.x * 64;
    const int nBase = blockIdx.y * 64;
    const int wm = (warp >> 1) * 32;
    const int wn = (warp & 1) * 32;

    if (mode == 1) {
        for (int i = tid; i < NOUT * 64; i += 128) {
            int o = i >> 6, c = i & 63;
            w3s[o][c] = w3[o * HID + nBase + c];
        }
    }

    uint32_t acc[2][4][2];      // f16x2 accumulators
    #pragma unroll
    for (int i = 0; i < 2; i++)
        #pragma unroll
        for (int j = 0; j < 4; j++) { acc[i][j][0] = 0u; acc[i][j][1] = 0u; }

    load_stage(smem, smem + A_TILE, A, Bt, mBase, nBase, 0, tid);
    load_stage(smem + STAGE_BYTES, smem + STAGE_BYTES + A_TILE, A, Bt, mBase, nBase, KCHUNK, tid);

    const uint32_t aLane = (uint32_t)((wm + (lane & 15)) * T_ROWB + (lane >> 4) * 16);
    const uint32_t bLane = (uint32_t)((lane & 15) * T_ROWB + (lane >> 4) * 16);

    for (int it = 0; it < NITER; ++it) {
        if (it == NITER - 1)
            asm volatile("cp.async.wait_group 0;" ::: "memory");
        else
            asm volatile("cp.async.wait_group 1;" ::: "memory");
        __syncthreads();

        if (it + 2 < NITER) {
            uint32_t s = smem + (uint32_t)((it + 2) % 3) * STAGE_BYTES;
            load_stage(s, s + A_TILE, A, Bt, mBase, nBase, (it + 2) * KCHUNK, tid);
        }

        uint32_t sA = smem + (uint32_t)(it % 3) * STAGE_BYTES;
        uint32_t sB = sA + A_TILE;

        #pragma unroll
        for (int ks = 0; ks < 4; ks++) {
            uint32_t af[2][4], bfr[4][2];
            #pragma unroll
            for (int mi = 0; mi < 2; mi++)
                ldsm_x4(af[mi], sA + aLane + (uint32_t)(mi * 16 * T_ROWB + ks * 32));
            #pragma unroll
            for (int ni = 0; ni < 2; ni++) {
                uint32_t r[4];
                ldsm_x4(r, sB + bLane + (uint32_t)((wn + ni * 16) * T_ROWB + ks * 32));
                bfr[2 * ni][0] = r[0]; bfr[2 * ni][1] = r[2];
                bfr[2 * ni + 1][0] = r[1]; bfr[2 * ni + 1][1] = r[3];
            }
            #pragma unroll
            for (int mi = 0; mi < 2; mi++)
                #pragma unroll
                for (int nf = 0; nf < 4; nf++)
                    mma_fp8_f16(acc[mi][nf], af[mi], bfr[nf]);
        }
    }

    float invW = (float)rsqrt(g_acc[slotW]) * aScale;
    float invB = (float)rsqrt(g_acc[slotB]);
    int r0 = mBase + wm + (lane >> 2);
    int c0 = nBase + wn + (lane & 3) * 2;

    if (mode == 0) {
        #pragma unroll
        for (int mi = 0; mi < 2; mi++) {
            #pragma unroll
            for (int nf = 0; nf < 4; nf++) {
                int row = r0 + mi * 16;
                int col = c0 + nf * 8;
                float2 lo = __half22float2(*reinterpret_cast<__half2*>(&acc[mi][nf][0]));
                float2 hi = __half22float2(*reinterpret_cast<__half2*>(&acc[mi][nf][1]));
                float bb0 = bias[col] * invB;
                float bb1 = bias[col + 1] * invB;
                float v00 = fmaxf(lo.x * invW + bb0, 0.0f);
                float v01 = fmaxf(lo.y * invW + bb1, 0.0f);
                float v10 = fmaxf(hi.x * invW + bb0, 0.0f);
                float v11 = fmaxf(hi.y * invW + bb1, 0.0f);
                *reinterpret_cast<uint16_t*>(g_h1 + (size_t)row * HID + col) =
                    f2x_fp8(v00 * HSCALE, v01 * HSCALE);
                *reinterpret_cast<uint16_t*>(g_h1 + (size_t)(row + 8) * HID + col) =
                    f2x_fp8(v10 * HSCALE, v11 * HSCALE);
            }
        }
    } else {
        float p[4][NOUT];
        #pragma unroll
        for (int r = 0; r < 4; r++)
            #pragma unroll
            for (int o = 0; o < NOUT; o++) p[r][o] = 0.0f;
        #pragma unroll
        for (int mi = 0; mi < 2; mi++) {
            #pragma unroll
            for (int nf = 0; nf < 4; nf++) {
                int col = c0 + nf * 8;
                int cl = col - nBase;
                float2 lo = __half22float2(*reinterpret_cast<__half2*>(&acc[mi][nf][0]));
                float2 hi = __half22float2(*reinterpret_cast<__half2*>(&acc[mi][nf][1]));
                float bb0 = bias[col] * invB;
                float bb1 = bias[col + 1] * invB;
                float v00 = fmaxf(lo.x * invW + bb0, 0.0f);
                float v01 = fmaxf(lo.y * invW + bb1, 0.0f);
                float v10 = fmaxf(hi.x * invW + bb0, 0.0f);
                float v11 = fmaxf(hi.y * invW + bb1, 0.0f);
                #pragma unroll
                for (int o = 0; o < NOUT; o++) {
                    float w0 = w3s[o][cl], w1v = w3s[o][cl + 1];
                    p[mi * 2][o]     += v00 * w0 + v01 * w1v;
                    p[mi * 2 + 1][o] += v10 * w0 + v11 * w1v;
                }
            }
        }
        #pragma unroll
        for (int m = 1; m < 4; m <<= 1)
            #pragma unroll
            for (int r = 0; r < 4; r++)
                #pragma unroll
                for (int o = 0; o < NOUT; o++)
                    p[r][o] += __shfl_xor_sync(0xffffffffu, p[r][o], m);
        if ((lane & 3) == 0) {
            #pragma unroll
            for (int r = 0; r < 4; r++) {
                int row = r0 + (r & 1) * 8 + (r >> 1) * 16;
                #pragma unroll
                for (int o = 0; o < NOUT; o++)
                    atomicAdd(&g_yp[row * NOUT + o], p[(r >> 1) * 2 + (r & 1)][o]);
            }
        }
    }
}

// ---------------- final head: bias + log_softmax ------------------------------
__global__ void head_final_kernel(const float* __restrict__ b3, float* __restrict__ out) {
    int r = blockIdx.x * blockDim.x + threadIdx.x;
    if (r >= BATCH) return;
    float y[NOUT];
    #pragma unroll
    for (int o = 0; o < NOUT; o++) y[o] = g_yp[r * NOUT + o] + b3[o];
    float m = y[0];
    #pragma unroll
    for (int o = 1; o < NOUT; o++) m = fmaxf(m, y[o]);
    float s = 0.f;
    #pragma unroll
    for (int o = 0; o < NOUT; o++) s += expf(y[o] - m);
    float lse = m + logf(s);
    #pragma unroll
    for (int o = 0; o < NOUT; o++) out[r * NOUT + o] = y[o] - lse;
}

// ---------------- launch -----------------------------------------------------
extern "C" void kernel_launch(void* const* d_in, const int* in_sizes, int n_in,
                              void* d_out, int out_size) {
    const float* x    = (const float*)d_in[0];
    const float* w1   = (const float*)d_in[1];
    const float* lk1w = (const float*)d_in[2];
    const float* b1   = (const float*)d_in[3];
    const float* lk1b = (const float*)d_in[4];
    const float* w2   = (const float*)d_in[5];
    const float* lk2w = (const float*)d_in[6];
    const float* b2   = (const float*)d_in[7];
    const float* lk2b = (const float*)d_in[8];
    const float* w3   = (const float*)d_in[9];
    const float* w3r  = (const float*)d_in[10];
    const float* b3   = (const float*)d_in[11];
    const float* b3r  = (const float*)d_in[12];
    float* out = (float*)d_out;

    // 3 created streams (round-12 budget; more trips the mem guard)
    static cudaStream_t s2 = nullptr, s3 = nullptr, s4 = nullptr;
    static cudaEvent_t evF = nullptr, evS3 = nullptr, evW1a = nullptr, evW1b = nullptr,
                       evPrep2 = nullptr, evScal = nullptr, evG2h1 = nullptr;
    static int init_done = 0;
    if (!init_done) {
        cudaFuncSetAttribute(gemm_fp8_kernel, cudaFuncAttributeMaxDynamicSharedMemorySize, GEMM_SMEM);
        cudaStreamCreateWithFlags(&s2, cudaStreamNonBlocking);
        cudaStreamCreateWithFlags(&s3, cudaStreamNonBlocking);
        cudaStreamCreateWithFlags(&s4, cudaStreamNonBlocking);
        cudaEventCreateWithFlags(&evF, cudaEventDisableTiming);
        cudaEventCreateWithFlags(&evS3, cudaEventDisableTiming);
        cudaEventCreateWithFlags(&evW1a, cudaEventDisableTiming);
        cudaEventCreateWithFlags(&evW1b, cudaEventDisableTiming);
        cudaEventCreateWithFlags(&evPrep2, cudaEventDisableTiming);
        cudaEventCreateWithFlags(&evScal, cudaEventDisableTiming);
        cudaEventCreateWithFlags(&evG2h1, cudaEventDisableTiming);
        init_done = 1;
    }

    cudaStream_t ms = cudaStreamLegacy;
    {
        cudaStreamCaptureStatus st = cudaStreamCaptureStatusNone;
        cudaStreamIsCapturing(cudaStreamLegacy, &st);
        if (st != cudaStreamCaptureStatusActive) {
            cudaStreamCaptureStatus st2 = cudaStreamCaptureStatusNone;
            cudaStreamIsCapturing(cudaStreamPerThread, &st2);
            if (st2 == cudaStreamCaptureStatusActive) ms = cudaStreamPerThread;
        }
    }

    uint8_t *x8_p, *w1t_p, *w2t_p, *h1_p;
    cudaGetSymbolAddress((void**)&x8_p, g_x8);
    cudaGetSymbolAddress((void**)&w1t_p, g_w1t);
    cudaGetSymbolAddress((void**)&w2t_p, g_w2t);
    cudaGetSymbolAddress((void**)&h1_p, g_h1);

    dim3 wblk(32, 8);
    dim3 wgridHalf(HID / 64, HID / 128);
    dim3 wgridFull(HID / 32, HID / 128);
    dim3 gridHalf(BATCH / 128, HID / 64);    // 8 x 64 = 512 CTAs (512 rows)

    // fork: only the 8-double accumulator zeroing gates the wconv atomics
    zero_acc_kernel<<<1, 32, 0, ms>>>();
    cudaEventRecord(evF, ms);
    cudaStreamWaitEvent(s2, evF, 0);
    cudaStreamWaitEvent(s3, evF, 0);

    // s3: yp zeroing, ssq(b1), x conversion, then rho+scalars (short, off-path)
    zero_yp_kernel<<<(BATCH * NOUT + 255) / 256, 256, 0, s3>>>();
    sumsq_kernel<<<8, 256, 0, s3>>>((const float4*)b1, HID / 4, 1);
    xconv_kernel<<<(BATCH * HID / 16) / 256, 256, 0, s3>>>((const float4*)x, (uint4*)x8_p);
    cudaEventRecord(evS3, s3);
    rho_kernel<<<80, 256, 0, s3>>>(w3, w3r, b3, b3r);
    scalars_kernel<<<1, 1, 0, s3>>>(lk1w, lk1b, lk2w, lk2b, out);
    cudaEventRecord(evScal, s3);

    // ms: wconv1 half 0 (fused ssq slot 0)
    wconv_kernel<<<wgridHalf, wblk, 0, ms>>>(w1, w1t_p, 0, 0);
    cudaEventRecord(evW1a, ms);

    // s2: wconv1 half 1 (fused ssq), then gemm2-side prep
    wconv_kernel<<<wgridHalf, wblk, 0, s2>>>(w1, w1t_p, 0, HID / 2);
    cudaEventRecord(evW1b, s2);
    wconv_kernel<<<wgridFull, wblk, 0, s2>>>(w2, w2t_p, 2, 0);
    sumsq_kernel<<<8, 256, 0, s2>>>((const float4*)b2, HID / 4, 3);
    cudaEventRecord(evPrep2, s2);

    // ms: g1 half 0 (rows 0-511) -> g2 half 0 (chained; overlaps g1 half 1)
    cudaStreamWaitEvent(ms, evS3, 0);
    cudaStreamWaitEvent(ms, evW1b, 0);
    gemm_fp8_kernel<<<gridHalf, 128, GEMM_SMEM, ms>>>(x8_p, w1t_p, b1, w3, 0, 1.0f, 0, 1, 0);
    cudaStreamWaitEvent(ms, evPrep2, 0);
    gemm_fp8_kernel<<<gridHalf, 128, GEMM_SMEM, ms>>>(h1_p, w2t_p, b2, w3, 1, 1.0f / HSCALE, 2, 3, 0);

    // s4: g1 half 1 (rows 512-1023) -> g2 half 1
    cudaStreamWaitEvent(s4, evF, 0);
    cudaStreamWaitEvent(s4, evS3, 0);
    cudaStreamWaitEvent(s4, evW1a, 0);
    cudaStreamWaitEvent(s4, evW1b, 0);
    gemm_fp8_kernel<<<gridHalf, 128, GEMM_SMEM, s4>>>(x8_p, w1t_p, b1, w3, 0, 1.0f, 0, 1, BATCH / 2);
    cudaStreamWaitEvent(s4, evPrep2, 0);
    gemm_fp8_kernel<<<gridHalf, 128, GEMM_SMEM, s4>>>(h1_p, w2t_p, b2, w3, 1, 1.0f / HSCALE, 2, 3, BATCH / 2);
    cudaEventRecord(evG2h1, s4);

    // ms: join both g2 halves + scalars branch, then final head
    cudaStreamWaitEvent(ms, evG2h1, 0);
    head_final_kernel<<<BATCH / 128, 128, 0, ms>>>(b3, out);
    cudaStreamWaitEvent(ms, evScal, 0);
}